// round 14
// baseline (speedup 1.0000x reference)
#include <cuda_runtime.h>
#include <cuda_fp16.h>
#include <cstdint>

#define NB    16
#define NPOS  4096
#define CIN   512
#define DIMD  256
#define NTOT  (NB*NPOS)
#define NSPLIT 4

#define LDAH 72    // K-major smem row: 64 halves + 8 pad (144B)
#define LDBH 136   // MN-major 128-wide row (272B)
#define LDB2H 264  // MN-major 256-wide row (528B)

// stage sizes
#define STG_KM 55296   // A 128*72*2 (18432) + B 256*72*2 (36864)
#define AOFF_KM 18432
#define STG_GD 51200   // A 64*136*2 (17408) + B 64*264*2 (33792)
#define AOFF_GD 17408

// ---------------- scratch ----------------
__device__ __half g_xh[(size_t)NTOT*CIN];
__device__ __half g_qh[(size_t)NTOT*DIMD];
__device__ __half g_kh[(size_t)NTOT*DIMD];   // exp(k~)
__device__ __half g_vh[(size_t)NTOT*DIMD];   // exp(v~)
__device__ float g_part[2*8*NB*DIMD];
__device__ float g_krs [NB*DIMD];            // 1/S_k
__device__ float g_vrs [NB*DIMD];            // 4096/S_v
__device__ float g_gdp[(size_t)NSPLIT*NB*DIMD*DIMD];
__device__ __half g_gdh[(size_t)NB*DIMD*DIMD];
__device__ __half g_Wth [(size_t)3*DIMD*CIN];
__device__ __half g_Wrth[(size_t)CIN*DIMD];
__device__ __half g_Mth [(size_t)NB*CIN*DIMD];

// ---------------- helpers ----------------
__device__ __forceinline__ float exp_fast(float x) {
    float t = x * 1.4426950408889634f;
    t = fminf(fmaxf(t, -120.f), 120.f);
    float fi = rintf(t);
    float f  = t - fi;
    float p = 1.3333558146e-3f;
    p = fmaf(p, f, 9.6181291076e-3f);
    p = fmaf(p, f, 5.5504108665e-2f);
    p = fmaf(p, f, 2.4022650696e-1f);
    p = fmaf(p, f, 6.9314718056e-1f);
    p = fmaf(p, f, 1.0f);
    return __int_as_float(((int)fi + 127) << 23) * p;
}
__device__ __forceinline__ uint32_t smem_u32(const void* p) {
    uint32_t a;
    asm("{ .reg .u64 t; cvta.to.shared.u64 t, %1; cvt.u32.u64 %0, t; }" : "=r"(a) : "l"(p));
    return a;
}
__device__ __forceinline__ uint32_t f22h(float a, float b) {
    __half2 h = __floats2half2_rn(a, b);
    return *reinterpret_cast<uint32_t*>(&h);
}
#define CP16(sa, g) asm volatile("cp.async.cg.shared.global [%0], [%1], 16;" :: "r"(sa), "l"(g))
#define CPCOMMIT()  asm volatile("cp.async.commit_group;" ::: "memory")
#define CPWAIT0()   asm volatile("cp.async.wait_group 0;" ::: "memory")
__device__ __forceinline__ void ldsm4(uint32_t (&r)[4], uint32_t addr) {
    asm volatile("ldmatrix.sync.aligned.m8n8.x4.shared.b16 {%0,%1,%2,%3}, [%4];"
        : "=r"(r[0]), "=r"(r[1]), "=r"(r[2]), "=r"(r[3]) : "r"(addr));
}
__device__ __forceinline__ void ldsm4t(uint32_t (&r)[4], uint32_t addr) {
    asm volatile("ldmatrix.sync.aligned.m8n8.x4.trans.shared.b16 {%0,%1,%2,%3}, [%4];"
        : "=r"(r[0]), "=r"(r[1]), "=r"(r[2]), "=r"(r[3]) : "r"(addr));
}
__device__ __forceinline__ void mma16816(float* d, const uint32_t* a, const uint32_t* b) {
    asm volatile(
        "mma.sync.aligned.m16n8k16.row.col.f32.f16.f16.f32 "
        "{%0,%1,%2,%3},{%4,%5,%6,%7},{%8,%9},{%0,%1,%2,%3};"
        : "+f"(d[0]), "+f"(d[1]), "+f"(d[2]), "+f"(d[3])
        : "r"(a[0]), "r"(a[1]), "r"(a[2]), "r"(a[3]), "r"(b[0]), "r"(b[1]));
}

// ---------------- cp.async loaders (256 threads) ----------------
// K-major 128 rows x 64 halves
__device__ __forceinline__ void cpA128(uint32_t sb, const __half* __restrict__ g, int ld) {
#pragma unroll
    for (int j = 0; j < 4; j++) {
        int idx = threadIdx.x + j*256, m = idx >> 3, kq = (idx & 7) << 3;
        CP16(sb + (m*LDAH + kq)*2, g + (size_t)m*ld + kq);
    }
}
// K-major 256 rows x 64 halves
__device__ __forceinline__ void cpB256(uint32_t sb, const __half* __restrict__ g, int ld) {
#pragma unroll
    for (int j = 0; j < 8; j++) {
        int idx = threadIdx.x + j*256, m = idx >> 3, kq = (idx & 7) << 3;
        CP16(sb + (m*LDAH + kq)*2, g + (size_t)m*ld + kq);
    }
}
// MN-major 64 k-rows x 128 halves
__device__ __forceinline__ void cpT128(uint32_t sb, const __half* __restrict__ g, int ld) {
#pragma unroll
    for (int j = 0; j < 4; j++) {
        int idx = threadIdx.x + j*256, k = idx >> 4, nq = (idx & 15) << 3;
        CP16(sb + (k*LDBH + nq)*2, g + (size_t)k*ld + nq);
    }
}
// MN-major 64 k-rows x 256 halves
__device__ __forceinline__ void cpT256(uint32_t sb, const __half* __restrict__ g, int ld) {
#pragma unroll
    for (int j = 0; j < 8; j++) {
        int idx = threadIdx.x + j*256, k = idx >> 5, nq = (idx & 31) << 3;
        CP16(sb + (k*LDB2H + nq)*2, g + (size_t)k*ld + nq);
    }
}

// ---------------- compute: 8 warps 2x4, warp tile 64x64, one 32-K slab ----------------
__device__ __forceinline__ void compute_km(uint32_t Ab, uint32_t Bb, float (&acc)[4][8][4]) {
    const int lane = threadIdx.x & 31, warp = threadIdx.x >> 5;
    const int wm = (warp >> 2) * 64, wn = (warp & 3) * 64;
#pragma unroll
    for (int kk = 0; kk < 2; kk++) {
        int k0 = kk * 16;
        uint32_t a[4][4], b[8][2];
#pragma unroll
        for (int im = 0; im < 4; im++) {
            int m0 = wm + im * 16;
            ldsm4(a[im], Ab + (((m0 + ((lane>>3)&1)*8 + (lane&7)) * LDAH + k0 + (lane>>4)*8) << 1));
        }
#pragma unroll
        for (int p = 0; p < 4; p++) {
            int n0 = wn + p * 16;
            uint32_t r[4];
            ldsm4(r, Bb + (((n0 + ((lane>>4)&1)*8 + (lane&7)) * LDAH + k0 + ((lane>>3)&1)*8) << 1));
            b[2*p][0]=r[0]; b[2*p][1]=r[1]; b[2*p+1][0]=r[2]; b[2*p+1][1]=r[3];
        }
#pragma unroll
        for (int im = 0; im < 4; im++)
#pragma unroll
            for (int in = 0; in < 8; in++)
                mma16816(acc[im][in], a[im], b[in]);
    }
}
__device__ __forceinline__ void compute_T(uint32_t Ab, uint32_t Bb, float (&acc)[4][8][4]) {
    const int lane = threadIdx.x & 31, warp = threadIdx.x >> 5;
    const int wm = (warp >> 2) * 64, wn = (warp & 3) * 64;
#pragma unroll
    for (int kk = 0; kk < 2; kk++) {
        int k0 = kk * 16;
        uint32_t a[4][4], b[8][2];
#pragma unroll
        for (int im = 0; im < 4; im++) {
            int m0 = wm + im * 16;
            ldsm4t(a[im], Ab + (((k0 + ((lane>>4)&1)*8 + (lane&7)) * LDBH + m0 + ((lane>>3)&1)*8) << 1));
        }
#pragma unroll
        for (int p = 0; p < 4; p++) {
            int n0 = wn + p * 16;
            uint32_t r[4];
            ldsm4t(r, Bb + (((k0 + ((lane>>3)&1)*8 + (lane&7)) * LDB2H + n0 + ((lane>>4)&1)*8) << 1));
            b[2*p][0]=r[0]; b[2*p][1]=r[1]; b[2*p+1][0]=r[2]; b[2*p+1][1]=r[3];
        }
#pragma unroll
        for (int im = 0; im < 4; im++)
#pragma unroll
            for (int in = 0; in < 8; in++)
                mma16816(acc[im][in], a[im], b[in]);
    }
}
__device__ __forceinline__ void zacc(float (&acc)[4][8][4]) {
#pragma unroll
    for (int i = 0; i < 4; i++)
#pragma unroll
        for (int j = 0; j < 8; j++)
#pragma unroll
            for (int r = 0; r < 4; r++) acc[i][j][r] = 0.f;
}
__device__ __forceinline__ void epi_f(float* C, int ldc, float (&acc)[4][8][4],
                                      const float* bias, float scale) {
    const int lane = threadIdx.x & 31, warp = threadIdx.x >> 5;
    const int wm = (warp >> 2) * 64, wn = (warp & 3) * 64;
    const int g = lane >> 2, t = lane & 3;
#pragma unroll
    for (int im = 0; im < 4; im++)
#pragma unroll
        for (int in = 0; in < 8; in++) {
            int row = wm + im * 16 + g, col = wn + in * 8 + t * 2;
            float b0 = 0.f, b1 = 0.f;
            if (bias) { b0 = bias[col]; b1 = bias[col + 1]; }
            *(float2*)(C + (size_t)row * ldc + col) =
                make_float2(acc[im][in][0]*scale + b0, acc[im][in][1]*scale + b1);
            *(float2*)(C + (size_t)(row + 8) * ldc + col) =
                make_float2(acc[im][in][2]*scale + b0, acc[im][in][3]*scale + b1);
        }
}
__device__ __forceinline__ void epi_h(__half* C, int ldc, float (&acc)[4][8][4],
                                      const float* bias, int doexp, const float* colscale) {
    const int lane = threadIdx.x & 31, warp = threadIdx.x >> 5;
    const int wm = (warp >> 2) * 64, wn = (warp & 3) * 64;
    const int g = lane >> 2, t = lane & 3;
#pragma unroll
    for (int im = 0; im < 4; im++)
#pragma unroll
        for (int in = 0; in < 8; in++) {
            int row = wm + im * 16 + g, col = wn + in * 8 + t * 2;
            float b0 = bias ? bias[col] : 0.f, b1 = bias ? bias[col + 1] : 0.f;
            float v0 = acc[im][in][0] + b0, v1 = acc[im][in][1] + b1;
            float v2 = acc[im][in][2] + b0, v3 = acc[im][in][3] + b1;
            if (doexp) { v0 = exp_fast(v0); v1 = exp_fast(v1); v2 = exp_fast(v2); v3 = exp_fast(v3); }
            if (colscale) {
                float s0 = colscale[col], s1 = colscale[col + 1];
                v0 *= s0; v1 *= s1; v2 *= s0; v3 *= s1;
            }
            *(__half2*)(C + (size_t)row * ldc + col) = __floats2half2_rn(v0, v1);
            *(__half2*)(C + (size_t)(row + 8) * ldc + col) = __floats2half2_rn(v2, v3);
        }
}

// ---------------- 2-stage, 64-K-per-barrier GEMM body ----------------
#define GEMM64(CPA_EXPR, CPB_EXPR, COMPUTE2, STG, T)                           \
    do {                                                                       \
        { int i = 0; uint32_t st = s0; CPA_EXPR; CPB_EXPR; CPCOMMIT(); }       \
        CPWAIT0(); __syncthreads();                                            \
        for (int it = 0; it < (T); it++) {                                     \
            uint32_t cur = s0 + (it & 1) * STG;                                \
            if (it + 1 < (T)) {                                                \
                int i = it + 1; uint32_t st = s0 + ((it + 1) & 1) * STG;       \
                CPA_EXPR; CPB_EXPR; CPCOMMIT();                                \
            }                                                                  \
            COMPUTE2(cur);                                                     \
            if (it + 1 < (T)) { CPWAIT0(); }                                   \
            __syncthreads();                                                   \
        }                                                                      \
    } while (0)

#define COMP2_KM(cur)                                                          \
    do { compute_km((cur), (cur) + AOFF_KM, acc);                              \
         compute_km((cur) + 64, (cur) + AOFF_KM + 64, acc); } while (0)
#define COMP2_T(cur)                                                           \
    do { compute_T((cur), (cur) + AOFF_GD, acc);                               \
         compute_T((cur) + 8704, (cur) + AOFF_GD + 16896, acc); } while (0)

// ---------------- K0: x -> fp16 ----------------
__global__ void k_cvtx(const float* __restrict__ x) {
    size_t n8 = (size_t)NTOT * CIN / 8;
    for (size_t i = (size_t)blockIdx.x * blockDim.x + threadIdx.x; i < n8;
         i += (size_t)gridDim.x * blockDim.x) {
        const float4* s = (const float4*)(x + i * 8);
        float4 u = s[0], v = s[1];
        *(uint4*)(g_xh + i * 8) =
            make_uint4(f22h(u.x,u.y), f22h(u.z,u.w), f22h(v.x,v.y), f22h(v.z,v.w));
    }
}

// ---------------- weight transposes ----------------
__global__ void k_trw3(const float* __restrict__ Wq, const float* __restrict__ Wk,
                       const float* __restrict__ Wv) {
    __shared__ float t[32][33];
    const float* src = (blockIdx.z == 0) ? Wq : (blockIdx.z == 1) ? Wk : Wv;
    __half* dst = g_Wth + (size_t)blockIdx.z * DIMD * CIN;
    int bx = blockIdx.x * 32, by = blockIdx.y * 32;
    for (int j = threadIdx.y; j < 32; j += 8)
        t[j][threadIdx.x] = src[(size_t)(by + j) * DIMD + bx + threadIdx.x];
    __syncthreads();
    for (int j = threadIdx.y; j < 32; j += 8)
        dst[(size_t)(bx + j) * CIN + by + threadIdx.x] = __float2half_rn(t[threadIdx.x][j]);
}
__global__ void k_trh(const float* __restrict__ src, __half* __restrict__ dst, int R, int C) {
    __shared__ float t[32][33];
    int bx = blockIdx.x * 32, by = blockIdx.y * 32;
    for (int j = threadIdx.y; j < 32; j += 8)
        t[j][threadIdx.x] = src[(size_t)(by + j) * C + bx + threadIdx.x];
    __syncthreads();
    for (int j = threadIdx.y; j < 32; j += 8)
        dst[(size_t)(bx + j) * R + by + threadIdx.x] = __float2half_rn(t[threadIdx.x][j]);
}

// ---------------- K1: QKV projection (block 128x256) ----------------
__global__ __launch_bounds__(256, 1)
void k_proj(const float* __restrict__ bq, const float* __restrict__ bk,
            const float* __restrict__ bv) {
    extern __shared__ __align__(16) char smem[];
    int which = blockIdx.x, mt = blockIdx.y;
    const float* bias = (which == 0) ? bq : (which == 1) ? bk : bv;
    __half* out       = (which == 0) ? g_qh : (which == 1) ? g_kh : g_vh;
    const __half* A = g_xh + (size_t)mt * 128 * CIN;
    const __half* B = g_Wth + (size_t)which * DIMD * CIN;
    uint32_t s0 = smem_u32(smem);

    float acc[4][8][4];
    zacc(acc);
    GEMM64(cpA128(st, A + i * 64, CIN),
           cpB256(st + AOFF_KM, B + i * 64, CIN),
           COMP2_KM, STG_KM, CIN / 64);
    epi_h(out + (size_t)mt * 128 * DIMD, DIMD, acc, bias, which != 0, nullptr);
}

// ---------------- K2: column sums ----------------
__global__ void k_colsum() {
    int b = blockIdx.x >> 3, seg = blockIdx.x & 7, tensor = blockIdx.y;
    const __half* src = tensor ? g_vh : g_kh;
    int tid = threadIdx.x;
    const __half* p = src + ((size_t)b * NPOS + (size_t)seg * 512) * DIMD + tid;
    float s = 0.f;
#pragma unroll 4
    for (int n = 0; n < 512; n++)
        s += __half2float(p[(size_t)n * DIMD]);
    g_part[((size_t)tensor * 8 + seg) * (NB * DIMD) + b * DIMD + tid] = s;
}
__global__ void k_colfin() {
    int idx = blockIdx.x * 256 + threadIdx.x;
    int tensor = idx >> 12, j = idx & 4095;
    float S = 0.f;
#pragma unroll
    for (int seg = 0; seg < 8; seg++)
        S += g_part[((size_t)tensor * 8 + seg) * (NB * DIMD) + j];
    if (tensor == 0) g_krs[j] = 1.0f / S;
    else             g_vrs[j] = 4096.0f / S;
}

// ---------------- K3: gd partials (block 128x256) ----------------
__global__ __launch_bounds__(256, 1)
void k_gd() {
    extern __shared__ __align__(16) char smem[];
    int bid = blockIdx.x;
    int mt = bid & 1, sp = (bid >> 1) & (NSPLIT - 1), b = bid >> 3;
    const __half* Ka = g_kh + (size_t)b * NPOS * DIMD + mt * 128;
    const __half* Qa = g_qh + (size_t)b * NPOS * DIMD;
    const size_t nbase = (size_t)sp * (NPOS / NSPLIT);
    uint32_t s0 = smem_u32(smem);

    float acc[4][8][4];
    zacc(acc);
    GEMM64(cpT128(st, Ka + (nbase + (size_t)i * 64) * DIMD, DIMD),
           cpT256(st + AOFF_GD, Qa + (nbase + (size_t)i * 64) * DIMD, DIMD),
           COMP2_T, STG_GD, (NPOS / NSPLIT) / 64);
    epi_f(g_gdp + (((size_t)sp * NB + b) * DIMD + mt * 128) * DIMD,
          DIMD, acc, nullptr, 1.0f);
}
__global__ void k_gdreduce() {
    size_t i = ((size_t)blockIdx.x * blockDim.x + threadIdx.x) * 2;
    float s0 = 0.f, s1 = 0.f;
#pragma unroll
    for (int sp = 0; sp < NSPLIT; sp++) {
        const float* p = g_gdp + (size_t)sp * NB * DIMD * DIMD + i;
        s0 += p[0]; s1 += p[1];
    }
    float sc = g_krs[i >> 8];
    *(__half2*)(g_gdh + i) = __floats2half2_rn(s0 * sc, s1 * sc);
}

// ---------------- K4: Mth = (Wrt @ gdh^T) * (4096/S_v)  (block 128x256) ----------------
__global__ __launch_bounds__(256, 1)
void k_m() {
    extern __shared__ __align__(16) char smem[];
    int mt = blockIdx.x, b = blockIdx.y;
    const __half* A = g_Wrth + (size_t)mt * 128 * DIMD;
    const __half* B = g_gdh + (size_t)b * DIMD * DIMD;
    uint32_t s0 = smem_u32(smem);
    float acc[4][8][4];
    zacc(acc);
    GEMM64(cpA128(st, A + i * 64, DIMD),
           cpB256(st + AOFF_KM, B + i * 64, DIMD),
           COMP2_KM, STG_KM, DIMD / 64);
    epi_h(g_Mth + ((size_t)b * CIN + mt * 128) * DIMD, DIMD, acc,
          nullptr, 0, g_vrs + b * DIMD);
}

// ---------------- K5: out = exp(v) @ Mth^T * (1/4096) + br (block 128x256) ----------------
__global__ __launch_bounds__(256, 1)
void k_out(const float* __restrict__ br, float* __restrict__ out) {
    extern __shared__ __align__(16) char smem[];
    int nt = blockIdx.x, mt = blockIdx.y;
    int b = mt >> 5;
    const __half* A = g_vh + (size_t)mt * 128 * DIMD;
    const __half* B = g_Mth + ((size_t)b * CIN + nt * 256) * DIMD;
    uint32_t s0 = smem_u32(smem);
    float acc[4][8][4];
    zacc(acc);
    GEMM64(cpA128(st, A + i * 64, DIMD),
           cpB256(st + AOFF_KM, B + i * 64, DIMD),
           COMP2_KM, STG_KM, DIMD / 64);
    epi_f(out + (size_t)mt * 128 * CIN + nt * 256, CIN, acc, br + nt * 256,
          1.0f / 4096.0f);
}

// ---------------- launch ----------------
extern "C" void kernel_launch(void* const* d_in, const int* in_sizes, int n_in,
                              void* d_out, int out_size) {
    (void)in_sizes; (void)n_in; (void)out_size;
    const float* x  = (const float*)d_in[0];
    const float* Wq = (const float*)d_in[1];
    const float* bq = (const float*)d_in[2];
    const float* Wk = (const float*)d_in[3];
    const float* bk = (const float*)d_in[4];
    const float* Wv = (const float*)d_in[5];
    const float* bv = (const float*)d_in[6];
    const float* Wr = (const float*)d_in[7];
    const float* br = (const float*)d_in[8];
    float* out = (float*)d_out;

    static int smem_set = 0;
    if (!smem_set) {
        cudaFuncSetAttribute(k_proj, cudaFuncAttributeMaxDynamicSharedMemorySize, 2 * STG_KM);
        cudaFuncSetAttribute(k_gd,   cudaFuncAttributeMaxDynamicSharedMemorySize, 2 * STG_GD);
        cudaFuncSetAttribute(k_m,    cudaFuncAttributeMaxDynamicSharedMemorySize, 2 * STG_KM);
        cudaFuncSetAttribute(k_out,  cudaFuncAttributeMaxDynamicSharedMemorySize, 2 * STG_KM);
        smem_set = 1;
    }

    __half* wrt = nullptr;
    cudaGetSymbolAddress((void**)&wrt, g_Wrth);

    k_cvtx<<<2048, 256>>>(x);                                     // #1
    k_trw3<<<dim3(8, 16, 3), dim3(32, 8)>>>(Wq, Wk, Wv);          // #2
    k_trh<<<dim3(16, 8), dim3(32, 8)>>>(Wr, wrt, DIMD, CIN);      // #3
    k_proj<<<dim3(3, NTOT / 128), 256, 2 * STG_KM>>>(bq, bk, bv); // #4 (ncu slot)
    k_colsum<<<dim3(NB * 8, 2), 256>>>();
    k_colfin<<<32, 256>>>();
    k_gd<<<NB * NSPLIT * 2, 256, 2 * STG_GD>>>();
    k_gdreduce<<<(NB * DIMD * DIMD) / 512, 256>>>();
    k_m<<<dim3(4, NB), 256, 2 * STG_KM>>>();
    k_out<<<dim3(2, NTOT / 128), 256, 2 * STG_KM>>>(br, out);
}

// round 15
// speedup vs baseline: 1.3539x; 1.3539x over previous
#include <cuda_runtime.h>
#include <cuda_fp16.h>
#include <cstdint>

#define NB    16
#define NPOS  4096
#define CIN   512
#define DIMD  256
#define NTOT  (NB*NPOS)
#define NSPLIT 4

#define BK 32
#define LDAH 40    // K-major smem row: 32 halves + 8 pad (80B)
#define LDBH 136   // MN-major 128-wide row (272B)

#define STG_KM 20480   // A 128*40*2 + B 128*40*2
#define STG_GD 17408   // A 32*136*2 + B 32*136*2

// ---------------- scratch ----------------
__device__ __half g_xh[(size_t)NTOT*CIN];
__device__ __half g_qh[(size_t)NTOT*DIMD];
__device__ __half g_kh[(size_t)NTOT*DIMD];   // exp(k~) fp16 (unnormalized)
__device__ __half g_vh[(size_t)NTOT*DIMD];   // exp(v~) fp16 (unnormalized)
__device__ float g_ps[(size_t)2*512*256];    // per-(tensor, mt-tile) column partial sums
__device__ float g_krs [NB*DIMD];            // 1/S_k
__device__ float g_vrs [NB*DIMD];            // 4096/S_v
__device__ float g_gdp[(size_t)NSPLIT*NB*DIMD*DIMD];
__device__ __half g_gdh[(size_t)NB*DIMD*DIMD];   // normalized gd, fp16 [b][v][d]
__device__ __half g_Wth [(size_t)3*DIMD*CIN];    // [which][d][k=512]
__device__ __half g_Wrth[(size_t)CIN*DIMD];      // [c=512][d=256]
__device__ __half g_Mth [(size_t)NB*CIN*DIMD];   // [b][c][v]  (holds M*4096/S_v)

// ---------------- helpers ----------------
__device__ __forceinline__ float exp_fast(float x) {
    float t = x * 1.4426950408889634f;
    t = fminf(fmaxf(t, -120.f), 120.f);
    float fi = rintf(t);
    float f  = t - fi;
    float p = 1.3333558146e-3f;
    p = fmaf(p, f, 9.6181291076e-3f);
    p = fmaf(p, f, 5.5504108665e-2f);
    p = fmaf(p, f, 2.4022650696e-1f);
    p = fmaf(p, f, 6.9314718056e-1f);
    p = fmaf(p, f, 1.0f);
    return __int_as_float(((int)fi + 127) << 23) * p;
}
__device__ __forceinline__ uint32_t smem_u32(const void* p) {
    uint32_t a;
    asm("{ .reg .u64 t; cvta.to.shared.u64 t, %1; cvt.u32.u64 %0, t; }" : "=r"(a) : "l"(p));
    return a;
}
__device__ __forceinline__ uint32_t f22h(float a, float b) {
    __half2 h = __floats2half2_rn(a, b);
    return *reinterpret_cast<uint32_t*>(&h);
}
#define CP16(sa, g) asm volatile("cp.async.cg.shared.global [%0], [%1], 16;" :: "r"(sa), "l"(g))
#define CPCOMMIT()  asm volatile("cp.async.commit_group;" ::: "memory")
#define CPWAIT0()   asm volatile("cp.async.wait_group 0;" ::: "memory")
#define CPWAIT1()   asm volatile("cp.async.wait_group 1;" ::: "memory")
__device__ __forceinline__ void ldsm4(uint32_t (&r)[4], uint32_t addr) {
    asm volatile("ldmatrix.sync.aligned.m8n8.x4.shared.b16 {%0,%1,%2,%3}, [%4];"
        : "=r"(r[0]), "=r"(r[1]), "=r"(r[2]), "=r"(r[3]) : "r"(addr));
}
__device__ __forceinline__ void ldsm4t(uint32_t (&r)[4], uint32_t addr) {
    asm volatile("ldmatrix.sync.aligned.m8n8.x4.trans.shared.b16 {%0,%1,%2,%3}, [%4];"
        : "=r"(r[0]), "=r"(r[1]), "=r"(r[2]), "=r"(r[3]) : "r"(addr));
}
__device__ __forceinline__ void mma16816(float* d, const uint32_t* a, const uint32_t* b) {
    asm volatile(
        "mma.sync.aligned.m16n8k16.row.col.f32.f16.f16.f32 "
        "{%0,%1,%2,%3},{%4,%5,%6,%7},{%8,%9},{%0,%1,%2,%3};"
        : "+f"(d[0]), "+f"(d[1]), "+f"(d[2]), "+f"(d[3])
        : "r"(a[0]), "r"(a[1]), "r"(a[2]), "r"(a[3]), "r"(b[0]), "r"(b[1]));
}

// ---------------- cp.async tile loaders (256 threads) ----------------
__device__ __forceinline__ void cp128(uint32_t sb, const __half* __restrict__ g, int ld) {
#pragma unroll
    for (int j = 0; j < 2; j++) {
        int idx = threadIdx.x + j*256, m = idx >> 2, kq = (idx & 3) << 3;
        CP16(sb + (m*LDAH + kq)*2, g + (size_t)m*ld + kq);
    }
}
__device__ __forceinline__ void cpT(uint32_t sb, const __half* __restrict__ g, int ld) {
#pragma unroll
    for (int j = 0; j < 2; j++) {
        int idx = threadIdx.x + j*256, k = idx >> 4, nq = (idx & 15) << 3;
        CP16(sb + (k*LDBH + nq)*2, g + (size_t)k*ld + nq);
    }
}

// ---------------- compute: 8 warps 2x4, warp tile 64x32 ----------------
__device__ __forceinline__ void compute_km(uint32_t Ab, uint32_t Bb, float (&acc)[4][4][4]) {
    const int lane = threadIdx.x & 31, warp = threadIdx.x >> 5;
    const int wm = (warp >> 2) * 64, wn = (warp & 3) * 32;
#pragma unroll
    for (int kk = 0; kk < 2; kk++) {
        int k0 = kk * 16;
        uint32_t a[4][4], b[4][2];
#pragma unroll
        for (int im = 0; im < 4; im++) {
            int m0 = wm + im * 16;
            ldsm4(a[im], Ab + (((m0 + ((lane>>3)&1)*8 + (lane&7)) * LDAH + k0 + (lane>>4)*8) << 1));
        }
#pragma unroll
        for (int p = 0; p < 2; p++) {
            int n0 = wn + p * 16;
            uint32_t r[4];
            ldsm4(r, Bb + (((n0 + ((lane>>4)&1)*8 + (lane&7)) * LDAH + k0 + ((lane>>3)&1)*8) << 1));
            b[2*p][0]=r[0]; b[2*p][1]=r[1]; b[2*p+1][0]=r[2]; b[2*p+1][1]=r[3];
        }
#pragma unroll
        for (int im = 0; im < 4; im++)
#pragma unroll
            for (int in = 0; in < 4; in++)
                mma16816(acc[im][in], a[im], b[in]);
    }
}
__device__ __forceinline__ void compute_T(uint32_t Ab, uint32_t Bb, float (&acc)[4][4][4]) {
    const int lane = threadIdx.x & 31, warp = threadIdx.x >> 5;
    const int wm = (warp >> 2) * 64, wn = (warp & 3) * 32;
#pragma unroll
    for (int kk = 0; kk < 2; kk++) {
        int k0 = kk * 16;
        uint32_t a[4][4], b[4][2];
#pragma unroll
        for (int im = 0; im < 4; im++) {
            int m0 = wm + im * 16;
            ldsm4t(a[im], Ab + (((k0 + ((lane>>4)&1)*8 + (lane&7)) * LDBH + m0 + ((lane>>3)&1)*8) << 1));
        }
#pragma unroll
        for (int p = 0; p < 2; p++) {
            int n0 = wn + p * 16;
            uint32_t r[4];
            ldsm4t(r, Bb + (((k0 + ((lane>>3)&1)*8 + (lane&7)) * LDBH + n0 + ((lane>>4)&1)*8) << 1));
            b[2*p][0]=r[0]; b[2*p][1]=r[1]; b[2*p+1][0]=r[2]; b[2*p+1][1]=r[3];
        }
#pragma unroll
        for (int im = 0; im < 4; im++)
#pragma unroll
            for (int in = 0; in < 4; in++)
                mma16816(acc[im][in], a[im], b[in]);
    }
}
__device__ __forceinline__ void zacc(float (&acc)[4][4][4]) {
#pragma unroll
    for (int i = 0; i < 4; i++)
#pragma unroll
        for (int j = 0; j < 4; j++)
#pragma unroll
            for (int r = 0; r < 4; r++) acc[i][j][r] = 0.f;
}
__device__ __forceinline__ void epi_f(float* C, int ldc, float (&acc)[4][4][4],
                                      const float* bias, float scale) {
    const int lane = threadIdx.x & 31, warp = threadIdx.x >> 5;
    const int wm = (warp >> 2) * 64, wn = (warp & 3) * 32;
    const int g = lane >> 2, t = lane & 3;
#pragma unroll
    for (int im = 0; im < 4; im++)
#pragma unroll
        for (int in = 0; in < 4; in++) {
            int row = wm + im * 16 + g, col = wn + in * 8 + t * 2;
            float b0 = 0.f, b1 = 0.f;
            if (bias) { b0 = bias[col]; b1 = bias[col + 1]; }
            *(float2*)(C + (size_t)row * ldc + col) =
                make_float2(acc[im][in][0]*scale + b0, acc[im][in][1]*scale + b1);
            *(float2*)(C + (size_t)(row + 8) * ldc + col) =
                make_float2(acc[im][in][2]*scale + b0, acc[im][in][3]*scale + b1);
        }
}
// f16 epilogue, no exp (q / Mth path); optional per-col scale
__device__ __forceinline__ void epi_h(__half* C, int ldc, float (&acc)[4][4][4],
                                      const float* bias, const float* colscale) {
    const int lane = threadIdx.x & 31, warp = threadIdx.x >> 5;
    const int wm = (warp >> 2) * 64, wn = (warp & 3) * 32;
    const int g = lane >> 2, t = lane & 3;
#pragma unroll
    for (int im = 0; im < 4; im++)
#pragma unroll
        for (int in = 0; in < 4; in++) {
            int row = wm + im * 16 + g, col = wn + in * 8 + t * 2;
            float b0 = bias ? bias[col] : 0.f, b1 = bias ? bias[col + 1] : 0.f;
            float v0 = acc[im][in][0] + b0, v1 = acc[im][in][1] + b1;
            float v2 = acc[im][in][2] + b0, v3 = acc[im][in][3] + b1;
            if (colscale) {
                float s0 = colscale[col], s1 = colscale[col + 1];
                v0 *= s0; v1 *= s1; v2 *= s0; v3 *= s1;
            }
            *(__half2*)(C + (size_t)row * ldc + col) = __floats2half2_rn(v0, v1);
            *(__half2*)(C + (size_t)(row + 8) * ldc + col) = __floats2half2_rn(v2, v3);
        }
}
// f16 epilogue with exp + fused per-block column sums (k/v path).
// s_red: 16*132 floats of smem (reuses dead pipeline stages). psum: 128 floats out.
__device__ __forceinline__ void epi_h_expsum(__half* C, int ldc, float (&acc)[4][4][4],
                                             const float* bias, float* s_red,
                                             float* __restrict__ psum) {
    const int lane = threadIdx.x & 31, warp = threadIdx.x >> 5;
    const int wm = (warp >> 2) * 64, wn = (warp & 3) * 32;
    const int g = lane >> 2, t = lane & 3;
    float cs0[4], cs1[4];   // per-in column partials (col, col+1)
#pragma unroll
    for (int in = 0; in < 4; in++) { cs0[in] = 0.f; cs1[in] = 0.f; }
#pragma unroll
    for (int im = 0; im < 4; im++)
#pragma unroll
        for (int in = 0; in < 4; in++) {
            int row = wm + im * 16 + g, col = wn + in * 8 + t * 2;
            float b0 = bias[col], b1 = bias[col + 1];
            float v0 = exp_fast(acc[im][in][0] + b0);
            float v1 = exp_fast(acc[im][in][1] + b1);
            float v2 = exp_fast(acc[im][in][2] + b0);
            float v3 = exp_fast(acc[im][in][3] + b1);
            cs0[in] += v0 + v2;
            cs1[in] += v1 + v3;
            *(__half2*)(C + (size_t)row * ldc + col) = __floats2half2_rn(v0, v1);
            *(__half2*)(C + (size_t)(row + 8) * ldc + col) = __floats2half2_rn(v2, v3);
        }
    // reduce across the 16 threads per column
    const int slot = (warp >> 2) * 8 + g;   // 0..15
#pragma unroll
    for (int in = 0; in < 4; in++) {
        int col = wn + in * 8 + t * 2;
        s_red[slot * 132 + col]     = cs0[in];
        s_red[slot * 132 + col + 1] = cs1[in];
    }
    __syncthreads();
    if (threadIdx.x < 128) {
        float S = 0.f;
#pragma unroll
        for (int s = 0; s < 16; s++) S += s_red[s * 132 + threadIdx.x];
        psum[threadIdx.x] = S;
    }
}

// ---------------- 3-stage pipelined GEMM body ----------------
#define GEMM3(CPA_EXPR, CPB_EXPR, COMPUTE, STG, BOFF, T)                       \
    do {                                                                       \
        { int i = 0; uint32_t st = s0;              CPA_EXPR; CPB_EXPR; CPCOMMIT(); } \
        { int i = 1; uint32_t st = s0 + STG;        CPA_EXPR; CPB_EXPR; CPCOMMIT(); } \
        CPWAIT1(); __syncthreads();                                            \
        for (int it = 0; it < (T); it++) {                                     \
            uint32_t cur = s0 + (it % 3) * STG;                                \
            if (it + 2 < (T)) {                                                \
                int i = it + 2; uint32_t st = s0 + ((it + 2) % 3) * STG;       \
                CPA_EXPR; CPB_EXPR; CPCOMMIT();                                \
            }                                                                  \
            COMPUTE(cur, cur + BOFF, acc);                                     \
            if (it + 2 < (T)) { CPWAIT1(); } else { CPWAIT0(); }               \
            __syncthreads();                                                   \
        }                                                                      \
    } while (0)

// ---------------- K0: x -> fp16 ----------------
__global__ void k_cvtx(const float* __restrict__ x) {
    size_t n8 = (size_t)NTOT * CIN / 8;
    for (size_t i = (size_t)blockIdx.x * blockDim.x + threadIdx.x; i < n8;
         i += (size_t)gridDim.x * blockDim.x) {
        const float4* s = (const float4*)(x + i * 8);
        float4 u = s[0], v = s[1];
        *(uint4*)(g_xh + i * 8) =
            make_uint4(f22h(u.x,u.y), f22h(u.z,u.w), f22h(v.x,v.y), f22h(v.z,v.w));
    }
}

// ---------------- weight transposes ----------------
__global__ void k_trw3(const float* __restrict__ Wq, const float* __restrict__ Wk,
                       const float* __restrict__ Wv) {
    __shared__ float t[32][33];
    const float* src = (blockIdx.z == 0) ? Wq : (blockIdx.z == 1) ? Wk : Wv;
    __half* dst = g_Wth + (size_t)blockIdx.z * DIMD * CIN;
    int bx = blockIdx.x * 32, by = blockIdx.y * 32;
    for (int j = threadIdx.y; j < 32; j += 8)
        t[j][threadIdx.x] = src[(size_t)(by + j) * DIMD + bx + threadIdx.x];
    __syncthreads();
    for (int j = threadIdx.y; j < 32; j += 8)
        dst[(size_t)(bx + j) * CIN + by + threadIdx.x] = __float2half_rn(t[threadIdx.x][j]);
}
__global__ void k_trh(const float* __restrict__ src, __half* __restrict__ dst, int R, int C) {
    __shared__ float t[32][33];
    int bx = blockIdx.x * 32, by = blockIdx.y * 32;
    for (int j = threadIdx.y; j < 32; j += 8)
        t[j][threadIdx.x] = src[(size_t)(by + j) * C + bx + threadIdx.x];
    __syncthreads();
    for (int j = threadIdx.y; j < 32; j += 8)
        dst[(size_t)(bx + j) * R + by + threadIdx.x] = __float2half_rn(t[threadIdx.x][j]);
}

// ---------------- K1: QKV projection (fused column sums for k/v) ----------------
__global__ __launch_bounds__(256, 2)
void k_proj(const float* __restrict__ bq, const float* __restrict__ bk,
            const float* __restrict__ bv) {
    extern __shared__ __align__(16) char smem[];
    int which = blockIdx.x >> 1, nt = blockIdx.x & 1, mt = blockIdx.y;
    const float* bias = ((which == 0) ? bq : (which == 1) ? bk : bv) + nt * 128;
    __half* out       = (which == 0) ? g_qh : (which == 1) ? g_kh : g_vh;
    const __half* A = g_xh + (size_t)mt * 128 * CIN;
    const __half* B = g_Wth + ((size_t)which * DIMD + nt * 128) * CIN;
    uint32_t s0 = smem_u32(smem);

    float acc[4][4][4];
    zacc(acc);
    GEMM3(cp128(st, A + i * BK, CIN), cp128(st + 10240, B + i * BK, CIN),
          compute_km, STG_KM, 10240, CIN / BK);
    if (which == 0) {
        epi_h(out + ((size_t)mt * 128) * DIMD + nt * 128, DIMD, acc, bias, nullptr);
    } else {
        // psum slot: [tensor][mt][nt*128 + col]
        float* psum = g_ps + (((size_t)(which - 1) * 512 + mt) * 256 + nt * 128);
        epi_h_expsum(out + ((size_t)mt * 128) * DIMD + nt * 128, DIMD, acc, bias,
                     (float*)smem, psum);
    }
}

// ---------------- K2: finalize column sums ----------------
__global__ void k_colfin() {
    int idx = blockIdx.x * 256 + threadIdx.x;       // 0..8191
    int tensor = idx >> 12, j = idx & 4095;         // j = b*256 + ch
    int b = j >> 8, ch = j & 255;
    float S = 0.f;
#pragma unroll
    for (int m = 0; m < 32; m++)
        S += g_ps[((size_t)tensor * 512 + b * 32 + m) * 256 + ch];
    if (tensor == 0) g_krs[j] = 1.0f / S;
    else             g_vrs[j] = 4096.0f / S;
}

// ---------------- K3: gd partials ----------------
__global__ __launch_bounds__(256, 2)
void k_gd() {
    extern __shared__ __align__(16) char smem[];
    int bid = blockIdx.x;
    int nt = bid & 1, mt = (bid >> 1) & 1, sp = (bid >> 2) & (NSPLIT - 1), b = bid >> 4;
    const __half* Ka = g_kh + (size_t)b * NPOS * DIMD + mt * 128;
    const __half* Qa = g_qh + (size_t)b * NPOS * DIMD + nt * 128;
    const size_t nbase = (size_t)sp * (NPOS / NSPLIT);
    uint32_t s0 = smem_u32(smem);

    float acc[4][4][4];
    zacc(acc);
    GEMM3(cpT(st, Ka + (nbase + i * BK) * DIMD, DIMD),
          cpT(st + 8704, Qa + (nbase + i * BK) * DIMD, DIMD),
          compute_T, STG_GD, 8704, (NPOS / NSPLIT) / BK);
    epi_f(g_gdp + (((size_t)sp * NB + b) * DIMD + mt * 128) * DIMD + nt * 128,
          DIMD, acc, nullptr, 1.0f);
}
__global__ void k_gdreduce() {
    size_t i = ((size_t)blockIdx.x * blockDim.x + threadIdx.x) * 2;
    float s0 = 0.f, s1 = 0.f;
#pragma unroll
    for (int sp = 0; sp < NSPLIT; sp++) {
        const float* p = g_gdp + (size_t)sp * NB * DIMD * DIMD + i;
        s0 += p[0]; s1 += p[1];
    }
    float sc = g_krs[i >> 8];
    *(__half2*)(g_gdh + i) = __floats2half2_rn(s0 * sc, s1 * sc);
}

// ---------------- K4: Mth[b][c][v] = (Wrt @ gdh^T) * (4096/S_v) ----------------
__global__ __launch_bounds__(256, 2)
void k_m() {
    extern __shared__ __align__(16) char smem[];
    int mt = blockIdx.x, nt = blockIdx.y, b = blockIdx.z;
    const __half* A = g_Wrth + (size_t)mt * 128 * DIMD;
    const __half* B = g_gdh + ((size_t)b * DIMD + nt * 128) * DIMD;
    uint32_t s0 = smem_u32(smem);
    float acc[4][4][4];
    zacc(acc);
    GEMM3(cp128(st, A + i * BK, DIMD), cp128(st + 10240, B + i * BK, DIMD),
          compute_km, STG_KM, 10240, DIMD / BK);
    epi_h(g_Mth + ((size_t)b * CIN + mt * 128) * DIMD + nt * 128, DIMD, acc,
          nullptr, g_vrs + b * DIMD + nt * 128);
}

// ---------------- K5: out = exp(v) @ Mth^T * (1/4096) + br ----------------
__global__ __launch_bounds__(256, 2)
void k_out(const float* __restrict__ br, float* __restrict__ out) {
    extern __shared__ __align__(16) char smem[];
    int nt = blockIdx.x, mt = blockIdx.y;
    int b = mt >> 5;
    const __half* A = g_vh + (size_t)mt * 128 * DIMD;
    const __half* B = g_Mth + ((size_t)b * CIN + nt * 128) * DIMD;
    uint32_t s0 = smem_u32(smem);
    float acc[4][4][4];
    zacc(acc);
    GEMM3(cp128(st, A + i * BK, DIMD), cp128(st + 10240, B + i * BK, DIMD),
          compute_km, STG_KM, 10240, DIMD / BK);
    epi_f(out + (size_t)mt * 128 * CIN + nt * 128, CIN, acc, br + nt * 128,
          1.0f / 4096.0f);
}

// ---------------- launch ----------------
extern "C" void kernel_launch(void* const* d_in, const int* in_sizes, int n_in,
                              void* d_out, int out_size) {
    (void)in_sizes; (void)n_in; (void)out_size;
    const float* x  = (const float*)d_in[0];
    const float* Wq = (const float*)d_in[1];
    const float* bq = (const float*)d_in[2];
    const float* Wk = (const float*)d_in[3];
    const float* bk = (const float*)d_in[4];
    const float* Wv = (const float*)d_in[5];
    const float* bv = (const float*)d_in[6];
    const float* Wr = (const float*)d_in[7];
    const float* br = (const float*)d_in[8];
    float* out = (float*)d_out;

    static int smem_set = 0;
    if (!smem_set) {
        cudaFuncSetAttribute(k_proj, cudaFuncAttributeMaxDynamicSharedMemorySize, 3 * STG_KM);
        cudaFuncSetAttribute(k_gd,   cudaFuncAttributeMaxDynamicSharedMemorySize, 3 * STG_GD);
        cudaFuncSetAttribute(k_m,    cudaFuncAttributeMaxDynamicSharedMemorySize, 3 * STG_KM);
        cudaFuncSetAttribute(k_out,  cudaFuncAttributeMaxDynamicSharedMemorySize, 3 * STG_KM);
        smem_set = 1;
    }

    __half* wrt = nullptr;
    cudaGetSymbolAddress((void**)&wrt, g_Wrth);

    k_cvtx<<<2048, 256>>>(x);                                     // #1
    k_trw3<<<dim3(8, 16, 3), dim3(32, 8)>>>(Wq, Wk, Wv);          // #2
    k_trh<<<dim3(16, 8), dim3(32, 8)>>>(Wr, wrt, DIMD, CIN);      // #3
    k_proj<<<dim3(6, NTOT / 128), 256, 3 * STG_KM>>>(bq, bk, bv); // #4 (ncu slot)
    k_colfin<<<32, 256>>>();
    k_gd<<<NB * NSPLIT * 2 * 2, 256, 3 * STG_GD>>>();
    k_gdreduce<<<(NB * DIMD * DIMD) / 512, 256>>>();
    k_m<<<dim3(4, 2, NB), 256, 3 * STG_KM>>>();
    k_out<<<dim3(4, NTOT / 128), 256, 3 * STG_KM>>>(br, out);
}